// round 3
// baseline (speedup 1.0000x reference)
#include <cuda_runtime.h>
#include <cuda_bf16.h>
#include <math.h>

// Problem constants
#define BATCH      8
#define NPTS       16384
#define NUM_CLASS  100
#define CONVEX_K   10
#define MSKEL      1000
#define MPAIRS     500
#define NGROUP     800                  // BATCH * NUM_CLASS

#define NBLK       296                  // 2 blocks per SM on 148 SMs
#define NTH        128
#define TILE_PTS   128
#define NTILES     1024                 // 131072 points / 128
// exact: NBLK*128 = 37888 = 37*1024, so (bid*128)/37 tiles mapping is exact

// ---------------- device scratch (static, no allocation) -------------------
__device__ float  g_cand[2 * NBLK * MSKEL];   // per (block,slot,m) min candidates
__device__ float  g_group_convex[NGROUP];
__device__ double g_block_cd[NBLK];

#define BIGF 3.0e38f

// ---------------- packed f32x2 helpers (FFMA2 path, sm_103a) ---------------
typedef unsigned long long ull;

__device__ __forceinline__ ull pk2(float lo, float hi) {
    ull r; asm("mov.b64 %0, {%1,%2};" : "=l"(r) : "f"(lo), "f"(hi)); return r;
}
__device__ __forceinline__ void up2(ull v, float& lo, float& hi) {
    asm("mov.b64 {%0,%1}, %2;" : "=f"(lo), "=f"(hi) : "l"(v));
}
__device__ __forceinline__ ull fma2(ull a, ull b, ull c) {
    ull d; asm("fma.rn.f32x2 %0, %1, %2, %3;" : "=l"(d) : "l"(a), "l"(b), "l"(c));
    return d;
}

// ============================================================================
// Fused persistent kernel: convex loss + both chamfer directions.
// ============================================================================
__global__ void __launch_bounds__(NTH)
fused_kernel(const float* __restrict__ xyz, const float* __restrict__ skel,
             const int* __restrict__ labels)
{
    __shared__ ulonglong2 s_skA[MPAIRS];  // (-2sx pair, -2sy pair)
    __shared__ ulonglong2 s_skB[MPAIRS];  // (-2sz pair,  ss  pair)
    __shared__ ulonglong2 s_ptA[TILE_PTS];// ((x,x), (y,y))
    __shared__ ulonglong2 s_ptB[TILE_PTS];// ((z,z), (pp,pp))
    __shared__ double     s_warp[NTH / 32];

    const int bid  = blockIdx.x;
    const int tid  = threadIdx.x;
    const int lane = tid & 31;

    // ------------------ convex-hull loss (2-3 groups per block) ------------
    {
        const int gs = (bid * 100) / 37;
        const int ge = ((bid + 1) * 100) / 37;
        for (int g = gs + tid; g < ge; g += NTH) {
            const int b = g / NUM_CLASS;
            const int c = g % NUM_CLASS;
            const float* p  = skel   + (size_t)(b * MSKEL + c * CONVEX_K) * 3;
            const int*   lb = labels + (b * MSKEL + c * CONVEX_K);
            float px[CONVEX_K], py[CONVEX_K], pz[CONVEX_K];
            int   lv[CONVEX_K];
            #pragma unroll
            for (int j = 0; j < CONVEX_K; ++j) {
                px[j] = p[3 * j + 0]; py[j] = p[3 * j + 1]; pz[j] = p[3 * j + 2];
                lv[j] = lb[j];
            }
            float acc = 0.0f;
            #pragma unroll
            for (int i = 0; i < CONVEX_K; ++i) {
                float md = BIGF;
                #pragma unroll
                for (int j = 0; j < CONVEX_K; ++j) {
                    if (lv[j] == 1) {
                        float dx = px[i] - px[j];
                        float dy = py[i] - py[j];
                        float dz = pz[i] - pz[j];
                        md = fminf(md, fmaf(dx, dx, fmaf(dy, dy, dz * dz)));
                    }
                }
                md = fminf(md, 100000.0f);
                if (lv[i] != 1) acc += md;
            }
            g_group_convex[g] = acc;
        }
    }

    // ------------------ persistent chamfer over tile range -----------------
    const int tstart = (bid * 128) / 37;
    const int tend   = ((bid + 1) * 128) / 37;
    const int b0     = tstart >> 7;      // first batch this block touches

    int    cur_b = -1;
    double accA  = 0.0;                  // point-direction distance sum
    ull    msx[4], msy[4], msz[4];
    float  mss[8], bm[8];
    #pragma unroll
    for (int k = 0; k < 8; ++k) { mss[k] = 0.0f; bm[k] = BIGF; }
    #pragma unroll
    for (int k = 0; k < 4; ++k) { msx[k] = 0; msy[k] = 0; msz[k] = 0; }

    for (int t = tstart; t < tend; ++t) {
        const int b = t >> 7;            // tile -> batch (128 tiles/batch)
        if (b != cur_b) {
            if (cur_b >= 0 && tid < 125) {      // flush first batch -> slot 0
                const int row = 2 * bid;
                #pragma unroll
                for (int k = 0; k < 8; ++k)
                    g_cand[row * MSKEL + 8 * tid + k] = bm[k] + mss[k];
            }
            __syncthreads();             // all readers of s_sk / s_pt done
            const float* sb = skel + (size_t)b * MSKEL * 3;
            for (int i = tid; i < MPAIRS; i += NTH) {
                float ax = sb[6 * i + 0], ay = sb[6 * i + 1], az = sb[6 * i + 2];
                float cx = sb[6 * i + 3], cy = sb[6 * i + 4], cz = sb[6 * i + 5];
                float ssa = fmaf(ax, ax, fmaf(ay, ay, az * az));
                float ssc = fmaf(cx, cx, fmaf(cy, cy, cz * cz));
                s_skA[i] = make_ulonglong2(pk2(-2.f * ax, -2.f * cx),
                                           pk2(-2.f * ay, -2.f * cy));
                s_skB[i] = make_ulonglong2(pk2(-2.f * az, -2.f * cz),
                                           pk2(ssa, ssc));
            }
            __syncthreads();
            if (tid < 125) {
                #pragma unroll
                for (int k = 0; k < 4; ++k) {
                    ulonglong2 A  = s_skA[4 * tid + k];
                    ulonglong2 Bq = s_skB[4 * tid + k];
                    msx[k] = A.x; msy[k] = A.y; msz[k] = Bq.x;
                    up2(Bq.y, mss[2 * k], mss[2 * k + 1]);
                    bm[2 * k] = BIGF; bm[2 * k + 1] = BIGF;
                }
            }
            cur_b = b;
        }
        __syncthreads();                 // previous tile's pass B done with s_pt

        const size_t pidx = (size_t)(t * TILE_PTS + tid) * 6;
        const float x = xyz[pidx + 0];
        const float y = xyz[pidx + 1];
        const float z = xyz[pidx + 2];
        const float pp = fmaf(x, x, fmaf(y, y, z * z));
        s_ptA[tid] = make_ulonglong2(pk2(x, x), pk2(y, y));
        s_ptB[tid] = make_ulonglong2(pk2(z, z), pk2(pp, pp));
        __syncthreads();

        // ---- pass A: this thread's point vs all 1000 skel (e = ss - 2p.s) --
        {
            const ull pxx = pk2(x, x), pyy = pk2(y, y), pzz = pk2(z, z);
            float m1 = BIGF, m2 = BIGF;
            #pragma unroll 4
            for (int i = 0; i < MPAIRS; ++i) {
                const ulonglong2 A  = s_skA[i];
                const ulonglong2 Bq = s_skB[i];
                ull e = fma2(pxx, A.x, fma2(pyy, A.y, fma2(pzz, Bq.x, Bq.y)));
                float ea, eb; up2(e, ea, eb);
                m1 = fminf(m1, ea); m2 = fminf(m2, eb);
            }
            accA += (double)sqrtf(fmaxf(fminf(m1, m2) + pp, 1e-12f));
        }

        // ---- pass B: this thread's 8 skel points vs the 128-pt tile --------
        if (tid < 125) {
            #pragma unroll 2
            for (int p = 0; p < TILE_PTS; ++p) {
                const ulonglong2 PA = s_ptA[p];
                const ulonglong2 PB = s_ptB[p];
                #pragma unroll
                for (int k = 0; k < 4; ++k) {
                    ull e = fma2(msx[k], PA.x,
                             fma2(msy[k], PA.y,
                              fma2(msz[k], PB.x, PB.y)));   // pp - 2 p.s
                    float ea, eb; up2(e, ea, eb);
                    bm[2 * k]     = fminf(bm[2 * k],     ea);
                    bm[2 * k + 1] = fminf(bm[2 * k + 1], eb);
                }
            }
        }
    }

    // ---- final flush of m-direction candidates ----
    if (tid < 125) {
        const int slot = (cur_b == b0) ? 0 : 1;
        const int row  = 2 * bid + slot;
        #pragma unroll
        for (int k = 0; k < 8; ++k)
            g_cand[row * MSKEL + 8 * tid + k] = bm[k] + mss[k];
        if (slot == 0) {                 // single-batch block: poison slot 1
            #pragma unroll
            for (int k = 0; k < 8; ++k)
                g_cand[(2 * bid + 1) * MSKEL + 8 * tid + k] = BIGF;
        }
    }

    // ---- block point-direction sum (fixed order) ----
    #pragma unroll
    for (int off = 16; off > 0; off >>= 1)
        accA += __shfl_down_sync(0xffffffffu, accA, off);
    if (lane == 0) s_warp[tid >> 5] = accA;
    __syncthreads();
    if (tid == 0)
        g_block_cd[bid] = s_warp[0] + s_warp[1] + s_warp[2] + s_warp[3];
}

// ============================================================================
// Finalize: reduce candidates per (batch, m), sqrt, combine all terms.
// ============================================================================
__global__ void __launch_bounds__(1024)
finalize_kernel(float* __restrict__ out)
{
    __shared__ unsigned char s_rb[2 * NBLK];
    __shared__ double        s_red[1024];
    const int tid = threadIdx.x;

    if (tid < 2 * NBLK) {                // row -> batch LUT (static mapping)
        const int bb = tid >> 1;
        const int st = (bb * 128) / 37;
        const int en = ((bb + 1) * 128) / 37;
        s_rb[tid] = (tid & 1) ? (unsigned char)((en - 1) >> 7)
                              : (unsigned char)(st >> 7);
    }
    __syncthreads();

    double acc = 0.0;                    // skel-direction d sum (this m, all b)
    if (tid < MSKEL) {
        int   cur = 0;
        float mn  = BIGF;
        #pragma unroll 4
        for (int r = 0; r < 2 * NBLK; ++r) {
            const float v = g_cand[r * MSKEL + tid];
            const int   b = s_rb[r];     // nondecreasing over r
            if (b != cur) {
                acc += (double)sqrtf(fmaxf(mn, 1e-12f));
                mn = BIGF; cur = b;
            }
            mn = fminf(mn, v);
        }
        acc += (double)sqrtf(fmaxf(mn, 1e-12f));
    }

    double accA = 0.0, accC = 0.0;
    for (int i = tid; i < NBLK; i += 1024) accA += g_block_cd[i];
    for (int i = tid; i < NGROUP; i += 1024) accC += g_group_convex[i];

    s_red[tid] = accC * (1.0 / (double)NGROUP) + (acc + accA) * (0.1 / (double)BATCH);
    __syncthreads();
    for (int s = 512; s > 0; s >>= 1) {
        if (tid < s) s_red[tid] += s_red[tid + s];
        __syncthreads();
    }
    if (tid == 0) out[0] = (float)s_red[0];
}

// ============================================================================
extern "C" void kernel_launch(void* const* d_in, const int* in_sizes, int n_in,
                              void* d_out, int out_size)
{
    const float* xyz    = (const float*)d_in[0];   // [8,16384,6]
    const float* skel   = (const float*)d_in[1];   // [8,1000,3]
    // d_in[2] = weights (unused by reference)
    const int*   labels = (const int*)d_in[3];     // [8,100,10]
    float* out = (float*)d_out;

    fused_kernel<<<NBLK, NTH>>>(xyz, skel, labels);
    finalize_kernel<<<1, 1024>>>(out);
}

// round 4
// speedup vs baseline: 2.2288x; 2.2288x over previous
#include <cuda_runtime.h>
#include <cuda_bf16.h>
#include <math.h>

// Problem constants
#define BATCH      8
#define NPTS       16384
#define NUM_CLASS  100
#define CONVEX_K   10
#define MSKEL      1000
#define MPAIRS     500
#define NGROUP     800                  // BATCH * NUM_CLASS

#define NBLK       296                  // 2 blocks per SM on 148 SMs
#define NTH        128
#define TILE_PTS   128
// tiles: 1024 total; block bid covers [bid*128/37, (bid+1)*128/37)
// 37b*128/37 == 128b exactly => each block's tiles lie in ONE batch;
// batch b is covered by exactly blocks [37b, 37b+37).
#define BLOCKS_PER_BATCH 37

// ---------------- device scratch (static, no allocation) -------------------
__device__ float  g_cand[NBLK * MSKEL];     // per (block, m) min candidates
__device__ float  g_group_convex[NGROUP];
__device__ double g_block_cd[NBLK];
__device__ double g_skel_partial[32];       // reduce_skel block partials

#define BIGF 3.0e38f

// ---------------- packed f32x2 helpers (FFMA2 path, sm_103a) ---------------
typedef unsigned long long ull;

__device__ __forceinline__ ull pk2(float lo, float hi) {
    ull r; asm("mov.b64 %0, {%1,%2};" : "=l"(r) : "f"(lo), "f"(hi)); return r;
}
__device__ __forceinline__ void up2(ull v, float& lo, float& hi) {
    asm("mov.b64 {%0,%1}, %2;" : "=f"(lo), "=f"(hi) : "l"(v));
}
__device__ __forceinline__ ull fma2(ull a, ull b, ull c) {
    ull d; asm("fma.rn.f32x2 %0, %1, %2, %3;" : "=l"(d) : "l"(a), "l"(b), "l"(c));
    return d;
}

// ============================================================================
// Kernel 1 (persistent): convex loss + both chamfer directions.
// ============================================================================
__global__ void __launch_bounds__(NTH)
fused_kernel(const float* __restrict__ xyz, const float* __restrict__ skel,
             const int* __restrict__ labels)
{
    __shared__ ulonglong2 s_skA[MPAIRS];   // (-2sx pair, -2sy pair)
    __shared__ ulonglong2 s_skB[MPAIRS];   // (-2sz pair,  ss  pair)
    __shared__ ulonglong2 s_ptA[TILE_PTS]; // ((x,x), (y,y))
    __shared__ ulonglong2 s_ptB[TILE_PTS]; // ((z,z), (pp,pp))
    __shared__ double     s_warp[NTH / 32];

    const int bid  = blockIdx.x;
    const int tid  = threadIdx.x;
    const int lane = tid & 31;

    // ------------------ convex-hull loss (2-3 groups per block) ------------
    {
        const int gs = (bid * 100) / 37;
        const int ge = ((bid + 1) * 100) / 37;
        for (int g = gs + tid; g < ge; g += NTH) {
            const int b = g / NUM_CLASS;
            const int c = g % NUM_CLASS;
            const float* p  = skel   + (size_t)(b * MSKEL + c * CONVEX_K) * 3;
            const int*   lb = labels + (b * MSKEL + c * CONVEX_K);
            float px[CONVEX_K], py[CONVEX_K], pz[CONVEX_K];
            int   lv[CONVEX_K];
            #pragma unroll
            for (int j = 0; j < CONVEX_K; ++j) {
                px[j] = p[3 * j + 0]; py[j] = p[3 * j + 1]; pz[j] = p[3 * j + 2];
                lv[j] = lb[j];
            }
            float acc = 0.0f;
            #pragma unroll
            for (int i = 0; i < CONVEX_K; ++i) {
                float md = BIGF;
                #pragma unroll
                for (int j = 0; j < CONVEX_K; ++j) {
                    if (lv[j] == 1) {
                        float dx = px[i] - px[j];
                        float dy = py[i] - py[j];
                        float dz = pz[i] - pz[j];
                        md = fminf(md, fmaf(dx, dx, fmaf(dy, dy, dz * dz)));
                    }
                }
                md = fminf(md, 100000.0f);
                if (lv[i] != 1) acc += md;
            }
            g_group_convex[g] = acc;
        }
    }

    // ------------------ chamfer over this block's tile range ---------------
    const int tstart = (bid * 128) / 37;
    const int tend   = ((bid + 1) * 128) / 37;
    const int b      = tstart >> 7;          // single batch for whole block

    // load skel for this batch once (folded -2 / ss)
    {
        const float* sb = skel + (size_t)b * MSKEL * 3;
        for (int i = tid; i < MPAIRS; i += NTH) {
            float ax = sb[6 * i + 0], ay = sb[6 * i + 1], az = sb[6 * i + 2];
            float cx = sb[6 * i + 3], cy = sb[6 * i + 4], cz = sb[6 * i + 5];
            float ssa = fmaf(ax, ax, fmaf(ay, ay, az * az));
            float ssc = fmaf(cx, cx, fmaf(cy, cy, cz * cz));
            s_skA[i] = make_ulonglong2(pk2(-2.f * ax, -2.f * cx),
                                       pk2(-2.f * ay, -2.f * cy));
            s_skB[i] = make_ulonglong2(pk2(-2.f * az, -2.f * cz),
                                       pk2(ssa, ssc));
        }
    }
    __syncthreads();

    // each thread owns 8 skel points (4 packed pairs) for pass B
    ull   msx[4], msy[4], msz[4];
    float mss[8], bm[8];
    if (tid < 125) {
        #pragma unroll
        for (int k = 0; k < 4; ++k) {
            ulonglong2 A  = s_skA[4 * tid + k];
            ulonglong2 Bq = s_skB[4 * tid + k];
            msx[k] = A.x; msy[k] = A.y; msz[k] = Bq.x;
            up2(Bq.y, mss[2 * k], mss[2 * k + 1]);
            bm[2 * k] = BIGF; bm[2 * k + 1] = BIGF;
        }
    }

    double accA = 0.0;                        // point-direction distance sum

    for (int t = tstart; t < tend; ++t) {
        __syncthreads();                      // prior pass B done with s_pt

        const size_t pidx = (size_t)(t * TILE_PTS + tid) * 6;
        const float x = xyz[pidx + 0];
        const float y = xyz[pidx + 1];
        const float z = xyz[pidx + 2];
        const float pp = fmaf(x, x, fmaf(y, y, z * z));
        s_ptA[tid] = make_ulonglong2(pk2(x, x), pk2(y, y));
        s_ptB[tid] = make_ulonglong2(pk2(z, z), pk2(pp, pp));
        __syncthreads();

        // ---- pass A: this thread's point vs all 1000 skel ----
        {
            const ull pxx = pk2(x, x), pyy = pk2(y, y), pzz = pk2(z, z);
            float m1 = BIGF, m2 = BIGF;
            #pragma unroll 4
            for (int i = 0; i < MPAIRS; ++i) {
                const ulonglong2 A  = s_skA[i];
                const ulonglong2 Bq = s_skB[i];
                ull e = fma2(pxx, A.x, fma2(pyy, A.y, fma2(pzz, Bq.x, Bq.y)));
                float ea, eb; up2(e, ea, eb);
                m1 = fminf(m1, ea); m2 = fminf(m2, eb);
            }
            accA += (double)sqrtf(fmaxf(fminf(m1, m2) + pp, 1e-12f));
        }

        // ---- pass B: this thread's 8 skel points vs the 128-pt tile ----
        if (tid < 125) {
            #pragma unroll 2
            for (int p = 0; p < TILE_PTS; ++p) {
                const ulonglong2 PA = s_ptA[p];
                const ulonglong2 PB = s_ptB[p];
                #pragma unroll
                for (int k = 0; k < 4; ++k) {
                    ull e = fma2(msx[k], PA.x,
                             fma2(msy[k], PA.y,
                              fma2(msz[k], PB.x, PB.y)));   // pp - 2 p.s
                    float ea, eb; up2(e, ea, eb);
                    bm[2 * k]     = fminf(bm[2 * k],     ea);
                    bm[2 * k + 1] = fminf(bm[2 * k + 1], eb);
                }
            }
        }
    }

    // ---- flush m-direction candidates (one row per block) ----
    if (tid < 125) {
        #pragma unroll
        for (int k = 0; k < 8; ++k)
            g_cand[bid * MSKEL + 8 * tid + k] = bm[k] + mss[k];
    }

    // ---- block point-direction sum (fixed order) ----
    #pragma unroll
    for (int off = 16; off > 0; off >>= 1)
        accA += __shfl_down_sync(0xffffffffu, accA, off);
    if (lane == 0) s_warp[tid >> 5] = accA;
    __syncthreads();
    if (tid == 0)
        g_block_cd[bid] = s_warp[0] + s_warp[1] + s_warp[2] + s_warp[3];
}

// ============================================================================
// Kernel 2: per-(b,m) 37-way min + sqrt, block-reduced partial sums.
// grid = 32 x 256 threads  (8192 threads cover 8000 (b,m) pairs)
// ============================================================================
__global__ void __launch_bounds__(256)
reduce_skel_kernel()
{
    __shared__ double s_red[256];
    const int tid = threadIdx.x;
    const int i   = blockIdx.x * 256 + tid;

    double d = 0.0;
    if (i < BATCH * MSKEL) {
        const int b = i / MSKEL;
        const int m = i - b * MSKEL;
        const float* base = g_cand + (size_t)(BLOCKS_PER_BATCH * b) * MSKEL + m;
        float mn = BIGF;
        #pragma unroll
        for (int j = 0; j < BLOCKS_PER_BATCH; ++j)
            mn = fminf(mn, base[(size_t)j * MSKEL]);
        d = (double)sqrtf(fmaxf(mn, 1e-12f));
    }
    s_red[tid] = d;
    __syncthreads();
    for (int s = 128; s > 0; s >>= 1) {
        if (tid < s) s_red[tid] += s_red[tid + s];
        __syncthreads();
    }
    if (tid == 0) g_skel_partial[blockIdx.x] = s_red[0];
}

// ============================================================================
// Kernel 3: combine everything.
// ============================================================================
__global__ void __launch_bounds__(256)
finalize_kernel(float* __restrict__ out)
{
    __shared__ double s_red[256];
    const int tid = threadIdx.x;

    double cd = 0.0;
    if (tid < 32) cd += g_skel_partial[tid];
    cd += g_block_cd[tid];                    // 296 slots
    if (tid < NBLK - 256) cd += g_block_cd[tid + 256];

    double cv = 0.0;
    for (int i = tid; i < NGROUP; i += 256)
        cv += (double)g_group_convex[i];

    s_red[tid] = cv * (1.0 / (double)NGROUP) + cd * (0.1 / (double)BATCH);
    __syncthreads();
    for (int s = 128; s > 0; s >>= 1) {
        if (tid < s) s_red[tid] += s_red[tid + s];
        __syncthreads();
    }
    if (tid == 0) out[0] = (float)s_red[0];
}

// ============================================================================
extern "C" void kernel_launch(void* const* d_in, const int* in_sizes, int n_in,
                              void* d_out, int out_size)
{
    const float* xyz    = (const float*)d_in[0];   // [8,16384,6]
    const float* skel   = (const float*)d_in[1];   // [8,1000,3]
    // d_in[2] = weights (unused by reference)
    const int*   labels = (const int*)d_in[3];     // [8,100,10]
    float* out = (float*)d_out;

    fused_kernel<<<NBLK, NTH>>>(xyz, skel, labels);
    reduce_skel_kernel<<<32, 256>>>();
    finalize_kernel<<<1, 256>>>(out);
}

// round 5
// speedup vs baseline: 2.6007x; 1.1669x over previous
#include <cuda_runtime.h>
#include <cuda_bf16.h>
#include <math.h>

// Problem constants
#define BATCH      8
#define NPTS       16384
#define NUM_CLASS  100
#define CONVEX_K   10
#define MSKEL      1000
#define MPAIRS     500
#define NGROUP     800                   // BATCH * NUM_CLASS

#define NTH        128
#define TILE_PTS   128
#define NTILES     1024                  // 131072 pts / 128; 128 tiles per batch
#define TILES_PER_BATCH 128

// ---------------- device scratch (static, no allocation) -------------------
__device__ float  g_cand[NTILES * MSKEL];     // per (tile-block, m) candidates
__device__ float  g_group_convex[NGROUP];
__device__ double g_block_cd[NTILES];
__device__ double g_skel_partial[32];

#define BIGF 3.0e38f

// ---------------- packed f32x2 helpers (FFMA2 path, sm_103a) ---------------
typedef unsigned long long ull;

__device__ __forceinline__ ull pk2(float lo, float hi) {
    ull r; asm("mov.b64 %0, {%1,%2};" : "=l"(r) : "f"(lo), "f"(hi)); return r;
}
__device__ __forceinline__ void up2(ull v, float& lo, float& hi) {
    asm("mov.b64 {%0,%1}, %2;" : "=f"(lo), "=f"(hi) : "l"(v));
}
__device__ __forceinline__ ull fma2(ull a, ull b, ull c) {
    ull d; asm("fma.rn.f32x2 %0, %1, %2, %3;" : "=l"(d) : "l"(a), "l"(b), "l"(c));
    return d;
}

// ============================================================================
// Kernel 1: one 128-point tile per block (1024 blocks -> ~7 blocks/SM).
// Convex loss handled by blocks 0..799 (one group each, 10 lanes cooperate).
// ============================================================================
__global__ void __launch_bounds__(NTH)
fused_kernel(const float* __restrict__ xyz, const float* __restrict__ skel,
             const int* __restrict__ labels)
{
    __shared__ ulonglong2 s_skA[MPAIRS];   // (-2sx pair, -2sy pair)
    __shared__ ulonglong2 s_skB[MPAIRS];   // (-2sz pair,  ss  pair)
    __shared__ ulonglong2 s_ptA[TILE_PTS]; // ((x,x), (y,y))
    __shared__ ulonglong2 s_ptB[TILE_PTS]; // ((z,z), (pp,pp))
    __shared__ double     s_warp[NTH / 32];

    const int bid  = blockIdx.x;           // == tile index
    const int tid  = threadIdx.x;
    const int lane = tid & 31;
    const int b    = bid >> 7;              // batch (128 tiles per batch)

    // ---------------- convex-hull loss: group bid, lanes 0..9 --------------
    if (bid < NGROUP && tid < 16) {
        float contrib = 0.0f;
        const int gb = bid / NUM_CLASS;
        const int gc = bid % NUM_CLASS;
        const float* p  = skel   + (size_t)(gb * MSKEL + gc * CONVEX_K) * 3;
        const int*   lb = labels + (gb * MSKEL + gc * CONVEX_K);
        if (tid < CONVEX_K) {
            const float xi = p[3 * tid + 0];
            const float yi = p[3 * tid + 1];
            const float zi = p[3 * tid + 2];
            float md = BIGF;
            #pragma unroll
            for (int j = 0; j < CONVEX_K; ++j) {
                if (lb[j] == 1) {
                    float dx = xi - p[3 * j + 0];
                    float dy = yi - p[3 * j + 1];
                    float dz = zi - p[3 * j + 2];
                    md = fminf(md, fmaf(dx, dx, fmaf(dy, dy, dz * dz)));
                }
            }
            md = fminf(md, 100000.0f);
            contrib = (lb[tid] != 1) ? md : 0.0f;
        }
        #pragma unroll
        for (int off = 8; off > 0; off >>= 1)
            contrib += __shfl_down_sync(0xffffu, contrib, off);
        if (tid == 0) g_group_convex[bid] = contrib;
    }

    // ---------------- skel -> smem (folded -2 / ss) -------------------------
    {
        const float* sb = skel + (size_t)b * MSKEL * 3;
        for (int i = tid; i < MPAIRS; i += NTH) {
            float ax = sb[6 * i + 0], ay = sb[6 * i + 1], az = sb[6 * i + 2];
            float cx = sb[6 * i + 3], cy = sb[6 * i + 4], cz = sb[6 * i + 5];
            float ssa = fmaf(ax, ax, fmaf(ay, ay, az * az));
            float ssc = fmaf(cx, cx, fmaf(cy, cy, cz * cz));
            s_skA[i] = make_ulonglong2(pk2(-2.f * ax, -2.f * cx),
                                       pk2(-2.f * ay, -2.f * cy));
            s_skB[i] = make_ulonglong2(pk2(-2.f * az, -2.f * cz),
                                       pk2(ssa, ssc));
        }
    }

    // ---------------- this thread's point -> smem ---------------------------
    const size_t pidx = (size_t)(bid * TILE_PTS + tid) * 6;
    const float x = xyz[pidx + 0];
    const float y = xyz[pidx + 1];
    const float z = xyz[pidx + 2];
    const float pp = fmaf(x, x, fmaf(y, y, z * z));
    s_ptA[tid] = make_ulonglong2(pk2(x, x), pk2(y, y));
    s_ptB[tid] = make_ulonglong2(pk2(z, z), pk2(pp, pp));
    __syncthreads();

    // ---------------- pass B setup: thread owns 8 skel pts (4 pairs) -------
    ull   msx[4], msy[4], msz[4];
    float mss[8], bm[8];
    if (tid < 125) {
        #pragma unroll
        for (int k = 0; k < 4; ++k) {
            ulonglong2 A  = s_skA[4 * tid + k];
            ulonglong2 Bq = s_skB[4 * tid + k];
            msx[k] = A.x; msy[k] = A.y; msz[k] = Bq.x;
            up2(Bq.y, mss[2 * k], mss[2 * k + 1]);
            bm[2 * k] = BIGF; bm[2 * k + 1] = BIGF;
        }
    }

    // ---------------- pass A: point vs all 1000 skel ------------------------
    double accA;
    {
        const ull pxx = pk2(x, x), pyy = pk2(y, y), pzz = pk2(z, z);
        float m1 = BIGF, m2 = BIGF, m3 = BIGF, m4 = BIGF;
        #pragma unroll 4
        for (int i = 0; i < MPAIRS; i += 2) {
            const ulonglong2 A0 = s_skA[i],     B0 = s_skB[i];
            const ulonglong2 A1 = s_skA[i + 1], B1 = s_skB[i + 1];
            ull e0 = fma2(pxx, A0.x, fma2(pyy, A0.y, fma2(pzz, B0.x, B0.y)));
            ull e1 = fma2(pxx, A1.x, fma2(pyy, A1.y, fma2(pzz, B1.x, B1.y)));
            float ea, eb;
            up2(e0, ea, eb); m1 = fminf(m1, ea); m2 = fminf(m2, eb);
            up2(e1, ea, eb); m3 = fminf(m3, ea); m4 = fminf(m4, eb);
        }
        float mn = fminf(fminf(m1, m2), fminf(m3, m4));
        accA = (double)sqrtf(fmaxf(mn + pp, 1e-12f));
    }

    // ---------------- pass B: thread's 8 skel pts vs 128-pt tile -----------
    if (tid < 125) {
        #pragma unroll 2
        for (int p = 0; p < TILE_PTS; ++p) {
            const ulonglong2 PA = s_ptA[p];
            const ulonglong2 PB = s_ptB[p];
            #pragma unroll
            for (int k = 0; k < 4; ++k) {
                ull e = fma2(msx[k], PA.x,
                         fma2(msy[k], PA.y,
                          fma2(msz[k], PB.x, PB.y)));   // pp - 2 p.s
                float ea, eb; up2(e, ea, eb);
                bm[2 * k]     = fminf(bm[2 * k],     ea);
                bm[2 * k + 1] = fminf(bm[2 * k + 1], eb);
            }
        }
        #pragma unroll
        for (int k = 0; k < 8; ++k)
            g_cand[(size_t)bid * MSKEL + 8 * tid + k] = bm[k] + mss[k];
    }

    // ---------------- block point-direction sum ----------------------------
    #pragma unroll
    for (int off = 16; off > 0; off >>= 1)
        accA += __shfl_down_sync(0xffffffffu, accA, off);
    if (lane == 0) s_warp[tid >> 5] = accA;
    __syncthreads();
    if (tid == 0)
        g_block_cd[bid] = s_warp[0] + s_warp[1] + s_warp[2] + s_warp[3];
}

// ============================================================================
// Kernel 2: per-(b,m) 128-way min + sqrt, block partial sums.
// grid = 32 x 256 (8192 threads cover 8000 (b,m))
// ============================================================================
__global__ void __launch_bounds__(256)
reduce_skel_kernel()
{
    __shared__ double s_red[256];
    const int tid = threadIdx.x;
    const int i   = blockIdx.x * 256 + tid;

    double d = 0.0;
    if (i < BATCH * MSKEL) {
        const int b = i / MSKEL;
        const int m = i - b * MSKEL;
        const float* base = g_cand + (size_t)(TILES_PER_BATCH * b) * MSKEL + m;
        float mn = BIGF;
        #pragma unroll 8
        for (int j = 0; j < TILES_PER_BATCH; ++j)
            mn = fminf(mn, base[(size_t)j * MSKEL]);
        d = (double)sqrtf(fmaxf(mn, 1e-12f));
    }
    s_red[tid] = d;
    __syncthreads();
    for (int s = 128; s > 0; s >>= 1) {
        if (tid < s) s_red[tid] += s_red[tid + s];
        __syncthreads();
    }
    if (tid == 0) g_skel_partial[blockIdx.x] = s_red[0];
}

// ============================================================================
// Kernel 3: combine everything.
// ============================================================================
__global__ void __launch_bounds__(256)
finalize_kernel(float* __restrict__ out)
{
    __shared__ double s_red[256];
    const int tid = threadIdx.x;

    double cd = 0.0;
    if (tid < 32) cd += g_skel_partial[tid];
    #pragma unroll
    for (int i = tid; i < NTILES; i += 256) cd += g_block_cd[i];

    double cv = 0.0;
    for (int i = tid; i < NGROUP; i += 256)
        cv += (double)g_group_convex[i];

    s_red[tid] = cv * (1.0 / (double)NGROUP) + cd * (0.1 / (double)BATCH);
    __syncthreads();
    for (int s = 128; s > 0; s >>= 1) {
        if (tid < s) s_red[tid] += s_red[tid + s];
        __syncthreads();
    }
    if (tid == 0) out[0] = (float)s_red[0];
}

// ============================================================================
extern "C" void kernel_launch(void* const* d_in, const int* in_sizes, int n_in,
                              void* d_out, int out_size)
{
    const float* xyz    = (const float*)d_in[0];   // [8,16384,6]
    const float* skel   = (const float*)d_in[1];   // [8,1000,3]
    // d_in[2] = weights (unused by reference)
    const int*   labels = (const int*)d_in[3];     // [8,100,10]
    float* out = (float*)d_out;

    fused_kernel<<<NTILES, NTH>>>(xyz, skel, labels);
    reduce_skel_kernel<<<32, 256>>>();
    finalize_kernel<<<1, 256>>>(out);
}

// round 7
// speedup vs baseline: 2.8609x; 1.1000x over previous
#include <cuda_runtime.h>
#include <cuda_bf16.h>
#include <math.h>

// Problem constants
#define BATCH      8
#define NPTS       16384
#define NUM_CLASS  100
#define CONVEX_K   10
#define MSKEL      1000
#define MPAIRS     500
#define NGROUP     800                   // BATCH * NUM_CLASS

#define NTH        128
#define TILE_PTS   256
#define NBLKS      512                   // 131072 pts / 256; 64 tiles per batch
#define TILES_PER_BATCH 64

// ---------------- device scratch (static, no allocation) -------------------
__device__ float  g_cand[NBLKS * MSKEL];      // per (tile-block, m) candidates
__device__ float  g_group_convex[NGROUP];
__device__ double g_block_cd[NBLKS];
__device__ double g_skel_partial[32];

#define BIGF 3.0e38f

// ---------------- packed f32x2 helpers (FFMA2 path, sm_103a) ---------------
typedef unsigned long long ull;

__device__ __forceinline__ ull pk2(float lo, float hi) {
    ull r; asm("mov.b64 %0, {%1,%2};" : "=l"(r) : "f"(lo), "f"(hi)); return r;
}
__device__ __forceinline__ void up2(ull v, float& lo, float& hi) {
    asm("mov.b64 {%0,%1}, %2;" : "=f"(lo), "=f"(hi) : "l"(v));
}
__device__ __forceinline__ ull fma2(ull a, ull b, ull c) {
    ull d; asm("fma.rn.f32x2 %0, %1, %2, %3;" : "=l"(d) : "l"(a), "l"(b), "l"(c));
    return d;
}

// ============================================================================
// Kernel 1: one 256-point tile per block; each thread owns TWO points (pass A)
// and EIGHT skel points (pass B). Convex loss: warp 0 handles groups bid
// (lanes 0-15) and bid+512 (lanes 16-31), 10 active lanes per half.
// ============================================================================
__global__ void __launch_bounds__(NTH)
fused_kernel(const float* __restrict__ xyz, const float* __restrict__ skel,
             const int* __restrict__ labels)
{
    __shared__ ulonglong2 s_skA[MPAIRS];   // (-2sx pair, -2sy pair)
    __shared__ ulonglong2 s_skB[MPAIRS];   // (-2sz pair,  ss  pair)
    __shared__ ulonglong2 s_ptA[TILE_PTS]; // ((x,x), (y,y))
    __shared__ ulonglong2 s_ptB[TILE_PTS]; // ((z,z), (pp,pp))
    __shared__ double     s_warp[NTH / 32];

    const int bid  = blockIdx.x;            // tile index (64 per batch)
    const int tid  = threadIdx.x;
    const int lane = tid & 31;
    const int b    = bid >> 6;               // batch

    // ---------------- this thread's TWO points (load first: deep MLP) ------
    const size_t base = (size_t)bid * TILE_PTS;
    const size_t pidx0 = (base + tid) * 6;
    const size_t pidx1 = (base + tid + NTH) * 6;
    const float x0 = xyz[pidx0 + 0], y0 = xyz[pidx0 + 1], z0 = xyz[pidx0 + 2];
    const float x1 = xyz[pidx1 + 0], y1 = xyz[pidx1 + 1], z1 = xyz[pidx1 + 2];

    // -------- convex-hull loss: warp 0, two groups per block ---------------
    if (tid < 32) {
        const int g   = (tid < 16) ? bid : bid + NBLKS;   // bid or bid+512
        const int sub = tid & 15;
        float contrib = 0.0f;
        if (g < NGROUP) {
            const int gb = g / NUM_CLASS;
            const int gc = g % NUM_CLASS;
            const float* p  = skel   + (size_t)(gb * MSKEL + gc * CONVEX_K) * 3;
            const int*   lb = labels + (gb * MSKEL + gc * CONVEX_K);
            if (sub < CONVEX_K) {
                const float xi = p[3 * sub + 0];
                const float yi = p[3 * sub + 1];
                const float zi = p[3 * sub + 2];
                float md = BIGF;
                #pragma unroll
                for (int j = 0; j < CONVEX_K; ++j) {
                    if (lb[j] == 1) {
                        float dx = xi - p[3 * j + 0];
                        float dy = yi - p[3 * j + 1];
                        float dz = zi - p[3 * j + 2];
                        md = fminf(md, fmaf(dx, dx, fmaf(dy, dy, dz * dz)));
                    }
                }
                md = fminf(md, 100000.0f);
                contrib = (lb[sub] != 1) ? md : 0.0f;
            }
        }
        // reduce within each 16-lane half (width=16 keeps halves separate)
        #pragma unroll
        for (int off = 8; off > 0; off >>= 1)
            contrib += __shfl_down_sync(0xffffffffu, contrib, off, 16);
        if (sub == 0 && g < NGROUP) g_group_convex[g] = contrib;
    }

    // ---------------- skel -> smem (folded -2 / ss) -------------------------
    {
        const float* sb = skel + (size_t)b * MSKEL * 3;
        for (int i = tid; i < MPAIRS; i += NTH) {
            float ax = sb[6 * i + 0], ay = sb[6 * i + 1], az = sb[6 * i + 2];
            float cx = sb[6 * i + 3], cy = sb[6 * i + 4], cz = sb[6 * i + 5];
            float ssa = fmaf(ax, ax, fmaf(ay, ay, az * az));
            float ssc = fmaf(cx, cx, fmaf(cy, cy, cz * cz));
            s_skA[i] = make_ulonglong2(pk2(-2.f * ax, -2.f * cx),
                                       pk2(-2.f * ay, -2.f * cy));
            s_skB[i] = make_ulonglong2(pk2(-2.f * az, -2.f * cz),
                                       pk2(ssa, ssc));
        }
    }

    // ---------------- points -> smem ---------------------------------------
    const float pp0 = fmaf(x0, x0, fmaf(y0, y0, z0 * z0));
    const float pp1 = fmaf(x1, x1, fmaf(y1, y1, z1 * z1));
    s_ptA[tid]       = make_ulonglong2(pk2(x0, x0), pk2(y0, y0));
    s_ptB[tid]       = make_ulonglong2(pk2(z0, z0), pk2(pp0, pp0));
    s_ptA[tid + NTH] = make_ulonglong2(pk2(x1, x1), pk2(y1, y1));
    s_ptB[tid + NTH] = make_ulonglong2(pk2(z1, z1), pk2(pp1, pp1));
    __syncthreads();

    // ---------------- pass B setup: thread owns 8 skel pts (4 pairs) -------
    ull   msx[4], msy[4], msz[4];
    float mss[8], bm[8];
    if (tid < 125) {
        #pragma unroll
        for (int k = 0; k < 4; ++k) {
            ulonglong2 A  = s_skA[4 * tid + k];
            ulonglong2 Bq = s_skB[4 * tid + k];
            msx[k] = A.x; msy[k] = A.y; msz[k] = Bq.x;
            up2(Bq.y, mss[2 * k], mss[2 * k + 1]);
            bm[2 * k] = BIGF; bm[2 * k + 1] = BIGF;
        }
    }

    // ---------------- pass A: 2 points vs all 1000 skel --------------------
    double accA;
    {
        const ull pxx0 = pk2(x0, x0), pyy0 = pk2(y0, y0), pzz0 = pk2(z0, z0);
        const ull pxx1 = pk2(x1, x1), pyy1 = pk2(y1, y1), pzz1 = pk2(z1, z1);
        float n0a = BIGF, n0b = BIGF, n1a = BIGF, n1b = BIGF;
        float n0c = BIGF, n0d = BIGF, n1c = BIGF, n1d = BIGF;
        #pragma unroll 2
        for (int i = 0; i < MPAIRS; i += 2) {
            const ulonglong2 A0 = s_skA[i],     B0 = s_skB[i];
            const ulonglong2 A1 = s_skA[i + 1], B1 = s_skB[i + 1];
            float ea, eb;
            ull e00 = fma2(pxx0, A0.x, fma2(pyy0, A0.y, fma2(pzz0, B0.x, B0.y)));
            ull e10 = fma2(pxx1, A0.x, fma2(pyy1, A0.y, fma2(pzz1, B0.x, B0.y)));
            ull e01 = fma2(pxx0, A1.x, fma2(pyy0, A1.y, fma2(pzz0, B1.x, B1.y)));
            ull e11 = fma2(pxx1, A1.x, fma2(pyy1, A1.y, fma2(pzz1, B1.x, B1.y)));
            up2(e00, ea, eb); n0a = fminf(n0a, ea); n0b = fminf(n0b, eb);
            up2(e10, ea, eb); n1a = fminf(n1a, ea); n1b = fminf(n1b, eb);
            up2(e01, ea, eb); n0c = fminf(n0c, ea); n0d = fminf(n0d, eb);
            up2(e11, ea, eb); n1c = fminf(n1c, ea); n1d = fminf(n1d, eb);
        }
        float mn0 = fminf(fminf(n0a, n0b), fminf(n0c, n0d));
        float mn1 = fminf(fminf(n1a, n1b), fminf(n1c, n1d));
        accA  = (double)sqrtf(fmaxf(mn0 + pp0, 1e-12f));
        accA += (double)sqrtf(fmaxf(mn1 + pp1, 1e-12f));
    }

    // ---------------- pass B: 8 owned skel pts vs 256-pt tile --------------
    if (tid < 125) {
        #pragma unroll 2
        for (int p = 0; p < TILE_PTS; ++p) {
            const ulonglong2 PA = s_ptA[p];
            const ulonglong2 PB = s_ptB[p];
            #pragma unroll
            for (int k = 0; k < 4; ++k) {
                ull e = fma2(msx[k], PA.x,
                         fma2(msy[k], PA.y,
                          fma2(msz[k], PB.x, PB.y)));   // pp - 2 p.s
                float ea, eb; up2(e, ea, eb);
                bm[2 * k]     = fminf(bm[2 * k],     ea);
                bm[2 * k + 1] = fminf(bm[2 * k + 1], eb);
            }
        }
        #pragma unroll
        for (int k = 0; k < 8; ++k)
            g_cand[(size_t)bid * MSKEL + 8 * tid + k] = bm[k] + mss[k];
    }

    // ---------------- block point-direction sum ----------------------------
    #pragma unroll
    for (int off = 16; off > 0; off >>= 1)
        accA += __shfl_down_sync(0xffffffffu, accA, off);
    if (lane == 0) s_warp[tid >> 5] = accA;
    __syncthreads();
    if (tid == 0)
        g_block_cd[bid] = s_warp[0] + s_warp[1] + s_warp[2] + s_warp[3];
}

// ============================================================================
// Kernel 2: per-(b,m) 64-way min + sqrt, block partial sums.
// grid = 32 x 256 (8192 threads cover 8000 (b,m))
// ============================================================================
__global__ void __launch_bounds__(256)
reduce_skel_kernel()
{
    __shared__ double s_red[256];
    const int tid = threadIdx.x;
    const int i   = blockIdx.x * 256 + tid;

    double d = 0.0;
    if (i < BATCH * MSKEL) {
        const int b = i / MSKEL;
        const int m = i - b * MSKEL;
        const float* bp = g_cand + (size_t)(TILES_PER_BATCH * b) * MSKEL + m;
        float mn = BIGF;
        #pragma unroll 8
        for (int j = 0; j < TILES_PER_BATCH; ++j)
            mn = fminf(mn, bp[(size_t)j * MSKEL]);
        d = (double)sqrtf(fmaxf(mn, 1e-12f));
    }
    s_red[tid] = d;
    __syncthreads();
    for (int s = 128; s > 0; s >>= 1) {
        if (tid < s) s_red[tid] += s_red[tid + s];
        __syncthreads();
    }
    if (tid == 0) g_skel_partial[blockIdx.x] = s_red[0];
}

// ============================================================================
// Kernel 3: combine everything.
// ============================================================================
__global__ void __launch_bounds__(256)
finalize_kernel(float* __restrict__ out)
{
    __shared__ double s_red[256];
    const int tid = threadIdx.x;

    double cd = 0.0;
    if (tid < 32) cd += g_skel_partial[tid];
    #pragma unroll
    for (int i = tid; i < NBLKS; i += 256) cd += g_block_cd[i];

    double cv = 0.0;
    for (int i = tid; i < NGROUP; i += 256)
        cv += (double)g_group_convex[i];

    s_red[tid] = cv * (1.0 / (double)NGROUP) + cd * (0.1 / (double)BATCH);
    __syncthreads();
    for (int s = 128; s > 0; s >>= 1) {
        if (tid < s) s_red[tid] += s_red[tid + s];
        __syncthreads();
    }
    if (tid == 0) out[0] = (float)s_red[0];
}

// ============================================================================
extern "C" void kernel_launch(void* const* d_in, const int* in_sizes, int n_in,
                              void* d_out, int out_size)
{
    const float* xyz    = (const float*)d_in[0];   // [8,16384,6]
    const float* skel   = (const float*)d_in[1];   // [8,1000,3]
    // d_in[2] = weights (unused by reference)
    const int*   labels = (const int*)d_in[3];     // [8,100,10]
    float* out = (float*)d_out;

    fused_kernel<<<NBLKS, NTH>>>(xyz, skel, labels);
    reduce_skel_kernel<<<32, 256>>>();
    finalize_kernel<<<1, 256>>>(out);
}